// round 17
// baseline (speedup 1.0000x reference)
#include <cuda_runtime.h>
#include <cuda_bf16.h>
#include <math.h>
#include <stdint.h>

// Problem constants
#define HID   1024
#define NH    16
#define DH    64
#define SEQ   4096
#define BATCH 2
#define WIN   512
#define MTOT  (BATCH*SEQ)          // 8192 tokens
#define XELEMS ((size_t)MTOT*HID)

// GEMM tiled operand layout: tile = 128 rows x 32 k-cols, 80B padded rows.
#define TILEBYTES 10240
#define NCH 32
#define NMB 64
#define NNB 8

// K/V attention tile images (144B padded rows, = attn smem layout)
#define KTILEB 9216                // 64 rows * 144
#define NKTILES 64                 // SEQ / 64

// ---------------------------------------------------------------------------
// Scratch (__device__ globals; no allocations allowed)
// ---------------------------------------------------------------------------
__device__ char g_XhiT[(size_t)NMB * NCH * TILEBYTES];
__device__ char g_XloT[(size_t)NMB * NCH * TILEBYTES];
__device__ char g_WhiT[(size_t)4 * NNB * NCH * TILEBYTES];
__device__ char g_WloT[(size_t)4 * NNB * NCH * TILEBYTES];
__device__ char g_AhiT[(size_t)NMB * NCH * TILEBYTES];
__device__ char g_AloT[(size_t)NMB * NCH * TILEBYTES];
// Q in [b,h,s,d], pre-scaled by 1/8
__device__ __nv_bfloat16 g_Qhi[XELEMS];
__device__ __nv_bfloat16 g_Qlo[XELEMS];
// K/V as 64x144B tile images
__device__ char g_KhiI[(size_t)BATCH * NH * NKTILES * KTILEB];
__device__ char g_KloI[(size_t)BATCH * NH * NKTILES * KTILEB];
__device__ char g_VhiI[(size_t)BATCH * NH * NKTILES * KTILEB];
__device__ char g_VloI[(size_t)BATCH * NH * NKTILES * KTILEB];

// ---------------------------------------------------------------------------
// PTX helpers (baseline PTX only — compute_103-safe)
// ---------------------------------------------------------------------------
__device__ __forceinline__ uint32_t smem_u32(const void* p) {
    uint32_t a;
    asm("{ .reg .u64 t; cvta.to.shared.u64 t, %1; cvt.u32.u64 %0, t; }" : "=r"(a) : "l"(p));
    return a;
}
__device__ __forceinline__ void cp16(uint32_t dst, const void* src) {
    asm volatile("cp.async.cg.shared.global [%0], [%1], 16;" :: "r"(dst), "l"(src));
}
#define CP_COMMIT() asm volatile("cp.async.commit_group;" ::: "memory")
template <int N>
__device__ __forceinline__ void cp_wait() {
    asm volatile("cp.async.wait_group %0;" :: "n"(N) : "memory");
}
__device__ __forceinline__ void ldsm_x4(uint32_t& r0, uint32_t& r1, uint32_t& r2, uint32_t& r3, uint32_t a) {
    asm volatile("ldmatrix.sync.aligned.m8n8.x4.shared.b16 {%0,%1,%2,%3}, [%4];"
                 : "=r"(r0), "=r"(r1), "=r"(r2), "=r"(r3) : "r"(a));
}
__device__ __forceinline__ void ldsm_x4_t(uint32_t& r0, uint32_t& r1, uint32_t& r2, uint32_t& r3, uint32_t a) {
    asm volatile("ldmatrix.sync.aligned.m8n8.x4.trans.shared.b16 {%0,%1,%2,%3}, [%4];"
                 : "=r"(r0), "=r"(r1), "=r"(r2), "=r"(r3) : "r"(a));
}
__device__ __forceinline__ void mma16816(float* c, const uint32_t* a, const uint32_t* b) {
    asm volatile(
        "mma.sync.aligned.m16n8k16.row.col.f32.bf16.bf16.f32 "
        "{%0,%1,%2,%3}, {%4,%5,%6,%7}, {%8,%9}, {%0,%1,%2,%3};"
        : "+f"(c[0]), "+f"(c[1]), "+f"(c[2]), "+f"(c[3])
        : "r"(a[0]), "r"(a[1]), "r"(a[2]), "r"(a[3]), "r"(b[0]), "r"(b[1]));
}
__device__ __forceinline__ uint32_t bfpack(float a, float b) {
    uint32_t r;
    asm("cvt.rn.bf16x2.f32 %0, %1, %2;" : "=r"(r) : "f"(b), "f"(a));
    return r;
}
// --- bulk-copy (1D TMA) + mbarrier ---
#define MBAR_INIT(a, n) asm volatile("mbarrier.init.shared.b64 [%0], %1;" :: "r"(a), "r"(n) : "memory")
#define FENCE_ASYNC()   asm volatile("fence.proxy.async.shared::cta;" ::: "memory")
__device__ __forceinline__ void mbar_expect_tx(uint32_t mbar, uint32_t bytes) {
    asm volatile("mbarrier.arrive.expect_tx.shared.b64 _, [%0], %1;" :: "r"(mbar), "r"(bytes) : "memory");
}
__device__ __forceinline__ void bulk_cp(uint32_t dst, const void* src, uint32_t bytes, uint32_t mbar) {
    asm volatile("cp.async.bulk.shared::cta.global.mbarrier::complete_tx::bytes [%0], [%1], %2, [%3];"
                 :: "r"(dst), "l"(src), "r"(bytes), "r"(mbar) : "memory");
}
__device__ __forceinline__ void mbar_wait(uint32_t addr, uint32_t parity) {
    asm volatile(
        "{ .reg .pred P1;\n"
        "W%=: mbarrier.try_wait.parity.acquire.cta.shared::cta.b64 P1, [%0], %1;\n"
        "@P1 bra.uni D%=;\n bra.uni W%=;\n D%=: }"
        :: "r"(addr), "r"(parity) : "memory");
}

// ---------------------------------------------------------------------------
// fp32 -> bf16 hi/lo split of x and the 4 weight matrices, GEMM-TILED output.
// ---------------------------------------------------------------------------
__global__ __launch_bounds__(256)
void split_kernel(const float* __restrict__ x,
                  const float* __restrict__ Wq, const float* __restrict__ Wk,
                  const float* __restrict__ Wv, const float* __restrict__ Wo)
{
    const int bid = blockIdx.x;
    const int tid = threadIdx.x;
    const int c4 = (tid & 7) * 4;

    const float* srcbase;
    char *dh, *dl;
    if (bid < NMB * NCH) {
        const int mb = bid >> 5, kc = bid & 31;
        srcbase = x + (size_t)(mb * 128) * HID + kc * 32;
        dh = g_XhiT + (size_t)bid * TILEBYTES;
        dl = g_XloT + (size_t)bid * TILEBYTES;
    } else {
        const int wb = bid - NMB * NCH;
        const int w = wb >> 8;
        const int rem = wb & 255;
        const int nb = rem >> 5, kc = rem & 31;
        const float* Ws[4] = {Wq, Wk, Wv, Wo};
        srcbase = Ws[w] + (size_t)(nb * 128) * HID + kc * 32;
        dh = g_WhiT + (size_t)wb * TILEBYTES;
        dl = g_WloT + (size_t)wb * TILEBYTES;
    }
#pragma unroll
    for (int i = 0; i < 4; i++) {
        const int r = (tid >> 3) + i * 32;
        float4 v = *(const float4*)(srcbase + (size_t)r * HID + c4);
        __nv_bfloat16 h0 = __float2bfloat16(v.x), h1 = __float2bfloat16(v.y);
        __nv_bfloat16 h2 = __float2bfloat16(v.z), h3 = __float2bfloat16(v.w);
        ushort4 uh, ul;
        uh.x = __bfloat16_as_ushort(h0); uh.y = __bfloat16_as_ushort(h1);
        uh.z = __bfloat16_as_ushort(h2); uh.w = __bfloat16_as_ushort(h3);
        ul.x = __bfloat16_as_ushort(__float2bfloat16(v.x - __bfloat162float(h0)));
        ul.y = __bfloat16_as_ushort(__float2bfloat16(v.y - __bfloat162float(h1)));
        ul.z = __bfloat16_as_ushort(__float2bfloat16(v.z - __bfloat162float(h2)));
        ul.w = __bfloat16_as_ushort(__float2bfloat16(v.w - __bfloat162float(h3)));
        const uint32_t off = (uint32_t)r * 80 + c4 * 2;
        *(ushort4*)(dh + off) = uh;
        *(ushort4*)(dl + off) = ul;
    }
}

// ---------------------------------------------------------------------------
// bf16-split GEMM via mma.sync. CTA tile 128x256, 256 threads (8 warps, 2x4),
// warp tile 64x64, BK=32. 3-stage bulk-copy pipeline (prefetch distance 2).
// MODE 0: fp32 out. MODE 1: bf16 hi/lo to [b,h,s,d] (Q).
// MODE 2: bf16 hi/lo to 64x144B K/V tile images.
// ---------------------------------------------------------------------------
#define BM 128
#define BN 256
#define RSB 80
#define TSB TILEBYTES               // 10240
#define STG (6 * TSB)               // 61440: Ahi,Alo, Bhi x2, Blo x2
#define GSMEM (3 * STG + 64)        // 184384
#define GTHREADS 256

template <int MODE>
__device__ __forceinline__ void gemm_body(
    const char* __restrict__ AhiT, const char* __restrict__ AloT,
    const char* __restrict__ BhiT, const char* __restrict__ BloT,
    float* __restrict__ C, char* __restrict__ Chi,
    char* __restrict__ Clo, float scale)
{
    extern __shared__ char smem[];
    const uint32_t sb = smem_u32(smem);
    const int tid = threadIdx.x;
    const int lane = tid & 31;
    const int wid = tid >> 5;            // 0..7
    const int wm0 = (wid & 1) * 64;
    const int wn0 = (wid >> 1) * 64;     // 0,64,128,192
    const int m0 = blockIdx.x * BM;
    const int n0 = blockIdx.y * BN;
    const size_t atb = (size_t)(m0 >> 7) * NCH;
    const size_t btb0 = (size_t)(n0 >> 7) * NCH;         // first n-block
    const size_t btb1 = btb0 + NCH;                      // second n-block
    const uint32_t mbb = sb + 3 * STG;

    if (tid == 0) { MBAR_INIT(mbb, 1); MBAR_INIT(mbb + 8, 1); MBAR_INIT(mbb + 16, 1); }
    FENCE_ASYNC();
    __syncthreads();

    float acc[4][8][4];
#pragma unroll
    for (int i = 0; i < 4; i++)
#pragma unroll
        for (int j = 0; j < 8; j++)
#pragma unroll
            for (int v = 0; v < 4; v++) acc[i][j][v] = 0.0f;

    // stage layout: +0 Ahi, +TSB Alo, +2TSB Bhi(nb0), +3TSB Bhi(nb1),
    //               +4TSB Blo(nb0), +5TSB Blo(nb1)
    auto issue = [&](int ch, int slot) {
        const uint32_t st = sb + (uint32_t)slot * STG;
        const uint32_t mb = mbb + (uint32_t)slot * 8;
        mbar_expect_tx(mb, STG);
        bulk_cp(st,           AhiT + (atb + ch) * TILEBYTES, TILEBYTES, mb);
        bulk_cp(st + TSB,     AloT + (atb + ch) * TILEBYTES, TILEBYTES, mb);
        bulk_cp(st + 2 * TSB, BhiT + (btb0 + ch) * TILEBYTES, TILEBYTES, mb);
        bulk_cp(st + 3 * TSB, BhiT + (btb1 + ch) * TILEBYTES, TILEBYTES, mb);
        bulk_cp(st + 4 * TSB, BloT + (btb0 + ch) * TILEBYTES, TILEBYTES, mb);
        bulk_cp(st + 5 * TSB, BloT + (btb1 + ch) * TILEBYTES, TILEBYTES, mb);
    };

    if (tid == 0) { issue(0, 0); issue(1, 1); }

    int ph[3] = {0, 0, 0};
    int slot = 0;

#pragma unroll 1
    for (int ch = 0; ch < NCH; ch++) {
        if (slot == 0)      { mbar_wait(mbb,      ph[0]); ph[0] ^= 1; }
        else if (slot == 1) { mbar_wait(mbb + 8,  ph[1]); ph[1] ^= 1; }
        else                { mbar_wait(mbb + 16, ph[2]); ph[2] ^= 1; }
        __syncthreads();   // stage data visible; slot (ch+2)%3 free (consumed at ch-1)
        if (tid == 0 && ch + 2 < NCH) {
            int ns = slot + 2; if (ns >= 3) ns -= 3;
            issue(ch + 2, ns);
        }

        const uint32_t st = sb + (uint32_t)slot * STG;
        const uint32_t sAh = st;
        const uint32_t sAl = st + TSB;
        const uint32_t bsel = (uint32_t)(wn0 >> 7) * TSB;   // n-block select
        const uint32_t sBh = st + 2 * TSB + bsel;
        const uint32_t sBl = st + 4 * TSB + bsel;
        const int nrl = wn0 & 64;                            // row base within tile

#pragma unroll
        for (int ks = 0; ks < 2; ks++) {
            const int arow = wm0 + (lane & 15);
            const int acolb = (ks * 16 + 8 * ((lane >> 4) & 1)) * 2;
            uint32_t ah[4][4], al[4][4];
#pragma unroll
            for (int i = 0; i < 4; i++) {
                const uint32_t off = (uint32_t)(arow + i * 16) * RSB + acolb;
                ldsm_x4(ah[i][0], ah[i][1], ah[i][2], ah[i][3], sAh + off);
                ldsm_x4(al[i][0], al[i][1], al[i][2], al[i][3], sAl + off);
            }
            uint32_t bh[8][2], bl[8][2];
#pragma unroll
            for (int jj = 0; jj < 4; jj++) {
                const int nrow = nrl + 8 * (jj * 2 + ((lane >> 4) & 1)) + (lane & 7);
                const int kcolb = (ks * 16 + 8 * ((lane >> 3) & 1)) * 2;
                const uint32_t off = (uint32_t)nrow * RSB + kcolb;
                ldsm_x4(bh[jj*2][0], bh[jj*2][1], bh[jj*2+1][0], bh[jj*2+1][1], sBh + off);
                ldsm_x4(bl[jj*2][0], bl[jj*2][1], bl[jj*2+1][0], bl[jj*2+1][1], sBl + off);
            }
#pragma unroll
            for (int i = 0; i < 4; i++)
#pragma unroll
                for (int j = 0; j < 8; j++) {
                    mma16816(acc[i][j], ah[i], bh[j]);
                    mma16816(acc[i][j], ah[i], bl[j]);
                    mma16816(acc[i][j], al[i], bh[j]);
                }
        }
        if (++slot == 3) slot = 0;
    }

    const int frow = lane >> 2;
    const int fcol = 2 * (lane & 3);
#pragma unroll
    for (int i = 0; i < 4; i++) {
#pragma unroll
        for (int j = 0; j < 8; j++) {
            const int m = m0 + wm0 + i * 16 + frow;
            const int n = n0 + wn0 + j * 8 + fcol;
            if (MODE == 0) {
                float* cp = C + (size_t)m * HID + n;
                *(float2*)cp = make_float2(acc[i][j][0], acc[i][j][1]);
                *(float2*)(cp + 8 * HID) = make_float2(acc[i][j][2], acc[i][j][3]);
            } else {
                const int b = m >> 12, s = m & (SEQ - 1);
                const int h = n >> 6, d = n & 63;
                float c0 = acc[i][j][0] * scale, c1 = acc[i][j][1] * scale;
                float c2 = acc[i][j][2] * scale, c3 = acc[i][j][3] * scale;
                __nv_bfloat16 h0 = __float2bfloat16(c0), h1 = __float2bfloat16(c1);
                __nv_bfloat16 h2 = __float2bfloat16(c2), h3 = __float2bfloat16(c3);
                ushort2 u0, u1, v0, v1;
                u0.x = __bfloat16_as_ushort(h0); u0.y = __bfloat16_as_ushort(h1);
                u1.x = __bfloat16_as_ushort(h2); u1.y = __bfloat16_as_ushort(h3);
                v0.x = __bfloat16_as_ushort(__float2bfloat16(c0 - __bfloat162float(h0)));
                v0.y = __bfloat16_as_ushort(__float2bfloat16(c1 - __bfloat162float(h1)));
                v1.x = __bfloat16_as_ushort(__float2bfloat16(c2 - __bfloat162float(h2)));
                v1.y = __bfloat16_as_ushort(__float2bfloat16(c3 - __bfloat162float(h3)));
                if (MODE == 1) {
                    __nv_bfloat16* Ch = (__nv_bfloat16*)Chi;
                    __nv_bfloat16* Cl = (__nv_bfloat16*)Clo;
                    const size_t base0 = (((size_t)(b * NH + h) * SEQ + s) * DH) + d;
                    const size_t base1 = base0 + 8 * DH;
                    *(ushort2*)(Ch + base0) = u0;
                    *(ushort2*)(Ch + base1) = u1;
                    *(ushort2*)(Cl + base0) = v0;
                    *(ushort2*)(Cl + base1) = v1;
                } else {
                    const size_t tile = (size_t)(b * NH + h) * NKTILES + (s >> 6);
                    const uint32_t ro = (uint32_t)(s & 63) * 144 + d * 2;
                    char* dh = Chi + tile * KTILEB + ro;
                    char* dl = Clo + tile * KTILEB + ro;
                    *(ushort2*)(dh)           = u0;
                    *(ushort2*)(dh + 8 * 144) = u1;
                    *(ushort2*)(dl)           = v0;
                    *(ushort2*)(dl + 8 * 144) = v1;
                }
            }
        }
    }
}

__global__ __launch_bounds__(GTHREADS, 1)
void qkv_mma_kernel()
{
    const int z = blockIdx.z;
    const size_t wsz = (size_t)NNB * NCH * TILEBYTES;
    if (z == 0)
        gemm_body<1>(g_XhiT, g_XloT, g_WhiT, g_WloT,
                     nullptr, (char*)g_Qhi, (char*)g_Qlo, 0.125f);
    else if (z == 1)
        gemm_body<2>(g_XhiT, g_XloT, g_WhiT + wsz, g_WloT + wsz,
                     nullptr, g_KhiI, g_KloI, 1.0f);
    else
        gemm_body<2>(g_XhiT, g_XloT, g_WhiT + 2 * wsz, g_WloT + 2 * wsz,
                     nullptr, g_VhiI, g_VloI, 1.0f);
}

__global__ __launch_bounds__(GTHREADS, 1)
void oproj_mma_kernel(float* __restrict__ out)
{
    const size_t wsz = (size_t)NNB * NCH * TILEBYTES;
    gemm_body<0>(g_AhiT, g_AloT, g_WhiT + 3 * wsz, g_WloT + 3 * wsz,
                 out, nullptr, nullptr, 1.0f);
}

// ---------------------------------------------------------------------------
// Flash attention via mma.sync (unchanged from round 16 — passing).
// ---------------------------------------------------------------------------
#define QT 128
#define TRB 144
#define TILEB (64 * TRB)              // 9216 == KTILEB
#define STAGEB (4 * TILEB)            // 36864 (Khi,Klo,Vhi,Vlo)
#define ASMEM (2 * STAGEB + 512 + 64)

__global__ __launch_bounds__(256, 2)
void attn_mma_kernel(const int* __restrict__ attn_mask)
{
    extern __shared__ char smem[];
    const uint32_t sb = smem_u32(smem);
    const int tid = threadIdx.x;
    const int lane = tid & 31;
    const int wid = tid >> 5;
    const int qb = blockIdx.x;
    const int h = blockIdx.y;
    const int b = blockIdx.z;
    const int q0 = qb * QT;
    const size_t bh = (size_t)(b * NH + h);
    const size_t headoff = bh * SEQ * DH;

    const char* KhiB = g_KhiI + bh * NKTILES * KTILEB;
    const char* KloB = g_KloI + bh * NKTILES * KTILEB;
    const char* VhiB = g_VhiI + bh * NKTILES * KTILEB;
    const char* VloB = g_VloI + bh * NKTILES * KTILEB;

    const uint32_t mbs0 = sb + 2 * STAGEB + 512;
    const uint32_t mbs1 = mbs0 + 8;

    if (tid == 0) { MBAR_INIT(mbs0, 1); MBAR_INIT(mbs1, 1); }
    FENCE_ASYNC();
    __syncthreads();

    // ---- stage Q tile (hi/lo) via cp16 from [b,h,s,d] ----
#pragma unroll
    for (int i = 0; i < 8; i++) {
        const int idx = tid + i * 256;
        const int t = idx >> 10;
        const int r = (idx >> 3) & 127;
        const int cc = idx & 7;
        const __nv_bfloat16* base = t ? g_Qlo : g_Qhi;
        cp16(sb + t * 18432 + r * TRB + cc * 16,
             base + headoff + (size_t)(q0 + r) * DH + cc * 8);
    }
    CP_COMMIT();
    cp_wait<0>();
    __syncthreads();

    uint32_t qh[4][4], ql[4][4];
    {
        const int arow = wid * 16 + (lane & 15);
#pragma unroll
        for (int ks = 0; ks < 4; ks++) {
            const uint32_t off = (uint32_t)arow * TRB + (ks * 16 + 8 * ((lane >> 4) & 1)) * 2;
            ldsm_x4(qh[ks][0], qh[ks][1], qh[ks][2], qh[ks][3], sb + off);
            ldsm_x4(ql[ks][0], ql[ks][1], ql[ks][2], ql[ks][3], sb + 18432 + off);
        }
    }
    __syncthreads();

    const int r0g = q0 + wid * 16 + (lane >> 2);
    const int r1g = r0g + 8;

    float m0r = -1e4f, m1r = -1e4f, l0 = 0.0f, l1 = 0.0f;
    float o[8][4];
#pragma unroll
    for (int j = 0; j < 8; j++)
#pragma unroll
        for (int v = 0; v < 4; v++) o[j][v] = 0.0f;

    const int clo = (2 * qb >= 8) ? (2 * qb - 8) : 0;
    const int chi = 2 * qb + 1;

    if (tid == 0) {
        mbar_expect_tx(mbs0, 4 * KTILEB);
        bulk_cp(sb,             KhiB + (size_t)clo * KTILEB, KTILEB, mbs0);
        bulk_cp(sb + TILEB,     KloB + (size_t)clo * KTILEB, KTILEB, mbs0);
        bulk_cp(sb + 2 * TILEB, VhiB + (size_t)clo * KTILEB, KTILEB, mbs0);
        bulk_cp(sb + 3 * TILEB, VloB + (size_t)clo * KTILEB, KTILEB, mbs0);
    }
    if (tid < 16)
        cp16(sb + 2 * STAGEB + tid * 16, attn_mask + b * SEQ + clo * 64 + tid * 4);
    CP_COMMIT();

    int phs[2] = {0, 0};

#pragma unroll 1
    for (int c = clo; c <= chi; c++) {
        const int st = (c - clo) & 1;
        mbar_wait(st == 0 ? mbs0 : mbs1, phs[st]);
        phs[st] ^= 1;
        cp_wait<0>();
        __syncthreads();
        if (c < chi) {
            const uint32_t nb = sb + (st ^ 1) * STAGEB;
            const uint32_t nm = (st == 0) ? mbs1 : mbs0;
            if (tid == 0) {
                mbar_expect_tx(nm, 4 * KTILEB);
                bulk_cp(nb,             KhiB + (size_t)(c + 1) * KTILEB, KTILEB, nm);
                bulk_cp(nb + TILEB,     KloB + (size_t)(c + 1) * KTILEB, KTILEB, nm);
                bulk_cp(nb + 2 * TILEB, VhiB + (size_t)(c + 1) * KTILEB, KTILEB, nm);
                bulk_cp(nb + 3 * TILEB, VloB + (size_t)(c + 1) * KTILEB, KTILEB, nm);
            }
            if (tid < 16)
                cp16(sb + 2 * STAGEB + (st ^ 1) * 256 + tid * 16,
                     attn_mask + b * SEQ + (c + 1) * 64 + tid * 4);
            CP_COMMIT();
        }

        const uint32_t kb = sb + st * STAGEB;

        float p[8][4];
#pragma unroll
        for (int j = 0; j < 8; j++)
#pragma unroll
            for (int v = 0; v < 4; v++) p[j][v] = 0.0f;

#pragma unroll
        for (int ks = 0; ks < 4; ks++) {
            uint32_t bh2[8][2], bl2[8][2];
#pragma unroll
            for (int jj = 0; jj < 4; jj++) {
                const int nrow = 16 * jj + 8 * ((lane >> 4) & 1) + (lane & 7);
                const int kcolb = (ks * 16 + 8 * ((lane >> 3) & 1)) * 2;
                const uint32_t off = (uint32_t)nrow * TRB + kcolb;
                ldsm_x4(bh2[jj*2][0], bh2[jj*2][1], bh2[jj*2+1][0], bh2[jj*2+1][1], kb + off);
                ldsm_x4(bl2[jj*2][0], bl2[jj*2][1], bl2[jj*2+1][0], bl2[jj*2+1][1], kb + TILEB + off);
            }
#pragma unroll
            for (int j = 0; j < 8; j++) {
                mma16816(p[j], qh[ks], bh2[j]);
                mma16816(p[j], qh[ks], bl2[j]);
                mma16816(p[j], ql[ks], bh2[j]);
            }
        }

        const int* mk = (const int*)(smem + 2 * STAGEB + st * 256);
        const int c64 = c * 64;
#pragma unroll
        for (int j = 0; j < 8; j++) {
            const int kloc = j * 8 + 2 * (lane & 3);
            const int kg = c64 + kloc;
            const int mv0 = mk[kloc], mv1 = mk[kloc + 1];
            if (!(kg     <= r0g && kg     >= r0g - (WIN-1) && mv0)) p[j][0] = -1e30f;
            if (!(kg + 1 <= r0g && kg + 1 >= r0g - (WIN-1) && mv1)) p[j][1] = -1e30f;
            if (!(kg     <= r1g && kg     >= r1g - (WIN-1) && mv0)) p[j][2] = -1e30f;
            if (!(kg + 1 <= r1g && kg + 1 >= r1g - (WIN-1) && mv1)) p[j][3] = -1e30f;
        }
        float mx0 = -1e30f, mx1 = -1e30f;
#pragma unroll
        for (int j = 0; j < 8; j++) {
            mx0 = fmaxf(mx0, fmaxf(p[j][0], p[j][1]));
            mx1 = fmaxf(mx1, fmaxf(p[j][2], p[j][3]));
        }
        mx0 = fmaxf(mx0, __shfl_xor_sync(0xffffffffu, mx0, 1));
        mx0 = fmaxf(mx0, __shfl_xor_sync(0xffffffffu, mx0, 2));
        mx1 = fmaxf(mx1, __shfl_xor_sync(0xffffffffu, mx1, 1));
        mx1 = fmaxf(mx1, __shfl_xor_sync(0xffffffffu, mx1, 2));

        const float mn0 = fmaxf(m0r, mx0);
        const float mn1 = fmaxf(m1r, mx1);
        const float cr0 = __expf(m0r - mn0);
        const float cr1 = __expf(m1r - mn1);
        m0r = mn0; m1r = mn1;
        l0 *= cr0; l1 *= cr1;
#pragma unroll
        for (int j = 0; j < 8; j++) {
            o[j][0] *= cr0; o[j][1] *= cr0;
            o[j][2] *= cr1; o[j][3] *= cr1;
        }
        float s0 = 0.0f, s1 = 0.0f;
#pragma unroll
        for (int j = 0; j < 8; j++) {
            p[j][0] = __expf(p[j][0] - mn0); s0 += p[j][0];
            p[j][1] = __expf(p[j][1] - mn0); s0 += p[j][1];
            p[j][2] = __expf(p[j][2] - mn1); s1 += p[j][2];
            p[j][3] = __expf(p[j][3] - mn1); s1 += p[j][3];
        }
        s0 += __shfl_xor_sync(0xffffffffu, s0, 1);
        s0 += __shfl_xor_sync(0xffffffffu, s0, 2);
        s1 += __shfl_xor_sync(0xffffffffu, s1, 1);
        s1 += __shfl_xor_sync(0xffffffffu, s1, 2);
        l0 += s0; l1 += s1;

#pragma unroll
        for (int ks2 = 0; ks2 < 4; ks2++) {
            uint32_t ahp[4], alp[4];
            {
                const float p00 = p[2*ks2][0],   p01 = p[2*ks2][1];
                const float p02 = p[2*ks2][2],   p03 = p[2*ks2][3];
                const float p10 = p[2*ks2+1][0], p11 = p[2*ks2+1][1];
                const float p12 = p[2*ks2+1][2], p13 = p[2*ks2+1][3];
                ahp[0] = bfpack(p00, p01);
                ahp[1] = bfpack(p02, p03);
                ahp[2] = bfpack(p10, p11);
                ahp[3] = bfpack(p12, p13);
                const __nv_bfloat162* hp0 = (const __nv_bfloat162*)&ahp[0];
                const __nv_bfloat162* hp1 = (const __nv_bfloat162*)&ahp[1];
                const __nv_bfloat162* hp2 = (const __nv_bfloat162*)&ahp[2];
                const __nv_bfloat162* hp3 = (const __nv_bfloat162*)&ahp[3];
                alp[0] = bfpack(p00 - __bfloat162float(hp0->x), p01 - __bfloat162float(hp0->y));
                alp[1] = bfpack(p02 - __bfloat162float(hp1->x), p03 - __bfloat162float(hp1->y));
                alp[2] = bfpack(p10 - __bfloat162float(hp2->x), p11 - __bfloat162float(hp2->y));
                alp[3] = bfpack(p12 - __bfloat162float(hp3->x), p13 - __bfloat162float(hp3->y));
            }
            uint32_t bvh[8][2], bvl[8][2];
#pragma unroll
            for (int jj = 0; jj < 4; jj++) {
                const int vrow = 16 * ks2 + (lane & 7) + 8 * ((lane >> 3) & 1);
                const int colb = (2 * jj + (lane >> 4)) * 16;
                const uint32_t off = (uint32_t)vrow * TRB + colb;
                ldsm_x4_t(bvh[jj*2][0], bvh[jj*2][1], bvh[jj*2+1][0], bvh[jj*2+1][1],
                          kb + 2 * TILEB + off);
                ldsm_x4_t(bvl[jj*2][0], bvl[jj*2][1], bvl[jj*2+1][0], bvl[jj*2+1][1],
                          kb + 3 * TILEB + off);
            }
#pragma unroll
            for (int j = 0; j < 8; j++) {
                mma16816(o[j], ahp, bvh[j]);
                mma16816(o[j], ahp, bvl[j]);
                mma16816(o[j], alp, bvh[j]);
            }
        }
    }

    // ---- normalize + write bf16 hi/lo in GEMM-tiled layout for oproj ----
    const float i0 = 1.0f / fmaxf(l0, 1e-30f);
    const float i1 = 1.0f / fmaxf(l1, 1e-30f);
    const int t0m = b * SEQ + r0g;
    const int mb = t0m >> 7;
    const int rit = t0m & 127;
    char* tbaseH = g_AhiT + (size_t)mb * NCH * TILEBYTES;
    char* tbaseL = g_AloT + (size_t)mb * NCH * TILEBYTES;
#pragma unroll
    for (int j = 0; j < 8; j++) {
        const int k = h * DH + j * 8 + 2 * (lane & 3);
        const int kc = k >> 5;
        const uint32_t off0 = (uint32_t)kc * TILEBYTES + (uint32_t)rit * 80 + (k & 31) * 2;
        const uint32_t off1 = off0 + 8 * 80;
        float a0 = o[j][0] * i0, a1 = o[j][1] * i0;
        float a2 = o[j][2] * i1, a3 = o[j][3] * i1;
        __nv_bfloat16 h0 = __float2bfloat16(a0), h1 = __float2bfloat16(a1);
        __nv_bfloat16 h2 = __float2bfloat16(a2), h3 = __float2bfloat16(a3);
        ushort2 u0, u1, v0, v1;
        u0.x = __bfloat16_as_ushort(h0); u0.y = __bfloat16_as_ushort(h1);
        u1.x = __bfloat16_as_ushort(h2); u1.y = __bfloat16_as_ushort(h3);
        v0.x = __bfloat16_as_ushort(__float2bfloat16(a0 - __bfloat162float(h0)));
        v0.y = __bfloat16_as_ushort(__float2bfloat16(a1 - __bfloat162float(h1)));
        v1.x = __bfloat16_as_ushort(__float2bfloat16(a2 - __bfloat162float(h2)));
        v1.y = __bfloat16_as_ushort(__float2bfloat16(a3 - __bfloat162float(h3)));
        *(ushort2*)(tbaseH + off0) = u0;
        *(ushort2*)(tbaseH + off1) = u1;
        *(ushort2*)(tbaseL + off0) = v0;
        *(ushort2*)(tbaseL + off1) = v1;
    }
}

// ---------------------------------------------------------------------------
// Launch
// ---------------------------------------------------------------------------
extern "C" void kernel_launch(void* const* d_in, const int* in_sizes, int n_in,
                              void* d_out, int out_size)
{
    const float* x    = (const float*)d_in[0];
    const int*   mask = (const int*)  d_in[1];
    const float* Wq   = (const float*)d_in[2];
    const float* Wk   = (const float*)d_in[3];
    const float* Wv   = (const float*)d_in[4];
    const float* Wo   = (const float*)d_in[5];
    float* out = (float*)d_out;

    static bool attr_set = false;
    if (!attr_set) {
        cudaFuncSetAttribute(qkv_mma_kernel,   cudaFuncAttributeMaxDynamicSharedMemorySize, GSMEM);
        cudaFuncSetAttribute(oproj_mma_kernel, cudaFuncAttributeMaxDynamicSharedMemorySize, GSMEM);
        cudaFuncSetAttribute(attn_mma_kernel,  cudaFuncAttributeMaxDynamicSharedMemorySize, ASMEM);
        attr_set = true;
    }

    split_kernel<<<NMB * NCH + 4 * NNB * NCH, 256>>>(x, Wq, Wk, Wv, Wo);

    dim3 qgrid(MTOT / BM, HID / BN, 3);
    qkv_mma_kernel<<<qgrid, GTHREADS, GSMEM>>>();

    dim3 agrid(SEQ / QT, NH, BATCH);
    attn_mma_kernel<<<agrid, 256, ASMEM>>>(mask);

    dim3 ogrid(MTOT / BM, HID / BN, 1);
    oproj_mma_kernel<<<ogrid, GTHREADS, GSMEM>>>(out);
}